// round 14
// baseline (speedup 1.0000x reference)
#include <cuda_runtime.h>
#include <math.h>

#define CC   16
#define DIMN 16
#define LL   6

typedef unsigned long long u64;

// ---------------- device-global precomputed params ----------------
// Deltas, cp-INNERMOST layout: entry (l, j, cp) holds dims {2j,2j+1} for c0=2cp, c1=2cp+1:
//   .x = ( -D_l[c0][2j],   -D_l[c1][2j]   )
//   .y = ( -D_l[c0][2j+1], -D_l[c1][2j+1] )   where -D_0 = -z0_0, -D_l = z0_{l-1}-z0_l
__device__ ulonglong2 g_negD2[LL * 8 * 8];   // index l*64 + j*8 + cp
__device__ ulonglong2 g_m52[8 * 8];          // (z0_5 - mean), index j*8 + cp
__device__ ulonglong2 g_parab[LL * 8];       // {(a_c0,a_c1), (b_c0,b_c1)}, index l*8+cp
__device__ u64        g_parc[LL * 8];        // (a*b) pair
__device__ u64        g_hld2[8];             // half_logdet pair
__device__ float      g_hld[CC];
__device__ float      g_Linv[CC * DIMN * DIMN];
__device__ int        g_ident;

// ---------------- f32x2 packed helpers (sm_103a) -------------------
__device__ __forceinline__ u64 pk2(float lo, float hi) {
    u64 r; asm("mov.b64 %0, {%1, %2};" : "=l"(r) : "f"(lo), "f"(hi)); return r;
}
__device__ __forceinline__ void up2(float& lo, float& hi, u64 v) {
    asm("mov.b64 {%0, %1}, %2;" : "=f"(lo), "=f"(hi) : "l"(v));
}
__device__ __forceinline__ u64 ffma2(u64 a, u64 b, u64 c) {
    u64 d; asm("fma.rn.f32x2 %0, %1, %2, %3;" : "=l"(d) : "l"(a), "l"(b), "l"(c)); return d;
}
__device__ __forceinline__ u64 add2(u64 a, u64 b) {
    u64 d; asm("add.rn.f32x2 %0, %1, %2;" : "=l"(d) : "l"(a), "l"(b)); return d;
}
__device__ __forceinline__ u64 mul2(u64 a, u64 b) {
    u64 d; asm("mul.rn.f32x2 %0, %1, %2;" : "=l"(d) : "l"(a), "l"(b)); return d;
}
__device__ __forceinline__ float fast_sqrt(float x) {
    float r; asm("sqrt.approx.f32 %0, %1;" : "=f"(r) : "f"(x)); return r;
}
__device__ __forceinline__ float fast_rcp(float x) {
    float r; asm("rcp.approx.f32 %0, %1;" : "=f"(r) : "f"(x)); return r;
}

// per-layer scalar tail: (e0+e1) -> r -> h -> f1,f2; updates P1,P2; returns f1 pair
__device__ __forceinline__ u64 tail_step(u64 e0, u64 e1, ulonglong2 pab, u64 abp,
                                         u64& P1p, u64& P2p) {
    const u64 ONE2 = pk2(1.0f, 1.0f);
    u64 r2p = add2(e0, e1);
    float rA, rB; up2(rA, rB, r2p);
    u64 rp = pk2(fast_sqrt(rA), fast_sqrt(rB));
    u64 up = add2(pab.x, rp);                 // alpha + r
    float uA, uB; up2(uA, uB, up);
    u64 hp = pk2(fast_rcp(uA), fast_rcp(uB));
    u64 f1p = ffma2(pab.y, hp, ONE2);         // 1 + beta*h
    u64 f2p = ffma2(abp, mul2(hp, hp), ONE2); // 1 + alpha*beta*h^2
    P1p = mul2(P1p, f1p);
    P2p = mul2(P2p, f2p);
    return f1p;
}

// ---------------- setup kernel (1 block) ----------------
__global__ void setup_kernel(const float* __restrict__ la, const float* __restrict__ be,
                             const float* __restrict__ z0, const float* __restrict__ mean,
                             const float* __restrict__ cov) {
    __shared__ int s_bad;
    int t = threadIdx.x;
    if (t == 0) s_bad = 0;
    __syncthreads();

    // packed params per (layer, c-pair)
    for (int i = t; i < LL * 8; i += 256) {
        int l = i / 8, cp = i % 8;
        int c0 = 2 * cp, c1 = c0 + 1;
        float a0 = expf(la[l * CC + c0]), a1 = expf(la[l * CC + c1]);
        float b0 = be[l * CC + c0],       b1 = be[l * CC + c1];
        ulonglong2 v; v.x = pk2(a0, a1); v.y = pk2(b0, b1);
        g_parab[i] = v;
        g_parc[i]  = pk2(a0 * b0, a1 * b1);
    }
    // layer deltas, cp-innermost: index l*64 + j*8 + cp
    for (int i = t; i < LL * 8 * 8; i += 256) {
        int l = i / 64, rem = i % 64, j = rem / 8, cp = rem % 8;
        int c0 = 2 * cp, c1 = c0 + 1;
        int b0 = (l * CC + c0) * DIMN + 2 * j;
        int b1 = (l * CC + c1) * DIMN + 2 * j;
        float x0 = -z0[b0], y0 = -z0[b0 + 1];
        float x1 = -z0[b1], y1 = -z0[b1 + 1];
        if (l > 0) {
            int p0 = ((l - 1) * CC + c0) * DIMN + 2 * j;
            int p1 = ((l - 1) * CC + c1) * DIMN + 2 * j;
            x0 += z0[p0]; y0 += z0[p0 + 1];
            x1 += z0[p1]; y1 += z0[p1 + 1];
        }
        ulonglong2 v; v.x = pk2(x0, x1); v.y = pk2(y0, y1);
        g_negD2[i] = v;
    }
    // final offset: z0_5 - mean, cp-innermost: index j*8 + cp
    for (int i = t; i < 8 * 8; i += 256) {
        int j = i / 8, cp = i % 8;
        int c0 = 2 * cp, c1 = c0 + 1;
        int b0 = (5 * CC + c0) * DIMN + 2 * j;
        int b1 = (5 * CC + c1) * DIMN + 2 * j;
        int m0 = c0 * DIMN + 2 * j, m1 = c1 * DIMN + 2 * j;
        ulonglong2 v;
        v.x = pk2(z0[b0]     - mean[m0],     z0[b1]     - mean[m1]);
        v.y = pk2(z0[b0 + 1] - mean[m0 + 1], z0[b1 + 1] - mean[m1 + 1]);
        g_m52[i] = v;
    }

    // cov identity check, vectorized (1024 float4, 4 per thread)
    int bad = 0;
    const float4* cv4 = (const float4*)cov;
    for (int i = t; i < CC * DIMN * DIMN / 4; i += 256) {
        float4 v = cv4[i];
        int base = i * 4;
        int r0 = base % (DIMN * DIMN);
        float e0 = ((r0 % (DIMN + 1)) == 0) ? 1.0f : 0.0f;
        float e1 = (((r0 + 1) % (DIMN + 1)) == 0) ? 1.0f : 0.0f;
        float e2 = (((r0 + 2) % (DIMN + 1)) == 0) ? 1.0f : 0.0f;
        float e3 = (((r0 + 3) % (DIMN + 1)) == 0) ? 1.0f : 0.0f;
        if (v.x != e0 || v.y != e1 || v.z != e2 || v.w != e3) bad = 1;
    }
    if (bad) atomicOr(&s_bad, 1);
    __syncthreads();
    int id = (s_bad == 0) ? 1 : 0;
    if (t == 0) g_ident = id;

    int c = t;
    if (c < CC) {
        if (id) {
            g_hld[c] = 0.0f;
        } else {
            // general Cholesky + triangular inverse (cold path)
            float Lm[DIMN][DIMN];
            const float* A = cov + c * DIMN * DIMN;
            #pragma unroll 1
            for (int j = 0; j < DIMN; j++) {
                float s = A[j * DIMN + j];
                #pragma unroll 1
                for (int k = 0; k < j; k++) s -= Lm[j][k] * Lm[j][k];
                float d = sqrtf(s);
                Lm[j][j] = d;
                float inv = 1.0f / d;
                #pragma unroll 1
                for (int i = j + 1; i < DIMN; i++) {
                    float s2 = A[i * DIMN + j];
                    #pragma unroll 1
                    for (int k = 0; k < j; k++) s2 -= Lm[i][k] * Lm[j][k];
                    Lm[i][j] = s2 * inv;
                }
            }
            float hld = 0.0f;
            #pragma unroll 1
            for (int j = 0; j < DIMN; j++) hld += logf(Lm[j][j]);
            g_hld[c] = hld;

            float Li[DIMN][DIMN];
            #pragma unroll 1
            for (int j = 0; j < DIMN; j++) {
                for (int i = 0; i < DIMN; i++) Li[i][j] = 0.0f;
                Li[j][j] = 1.0f / Lm[j][j];
                #pragma unroll 1
                for (int i = j + 1; i < DIMN; i++) {
                    float s3 = 0.0f;
                    #pragma unroll 1
                    for (int k = j; k < i; k++) s3 += Lm[i][k] * Li[k][j];
                    Li[i][j] = -s3 / Lm[i][i];
                }
            }
            for (int i = 0; i < DIMN; i++)
                for (int j = 0; j < DIMN; j++)
                    g_Linv[(c * DIMN + i) * DIMN + j] = Li[i][j];
        }
    }
    __syncthreads();
    if (t < 8) g_hld2[t] = pk2(g_hld[2 * t], g_hld[2 * t + 1]);
}

// ---------------- main density kernel: 1 thread per (n, c-pair), pipelined ----------------
__global__ void __launch_bounds__(256, 3)
density_kernel(const float* __restrict__ z, float* __restrict__ out, int N)
{
    __shared__ ulonglong2 s_negD[LL * 8 * 8];     // 6 KB, index l*64 + j*8 + cp
    __shared__ ulonglong2 s_m5[8 * 8];            // 1 KB, index j*8 + cp
    __shared__ ulonglong2 s_parab[LL * 8];        // 768 B
    __shared__ u64        s_parc[LL * 8];         // 384 B
    __shared__ u64        s_hld2[8];

    int t = threadIdx.x;
    for (int i = t; i < LL * 8 * 8; i += 256) s_negD[i] = g_negD2[i];
    if (t < 8 * 8) s_m5[t] = g_m52[t];
    if (t < LL * 8) { s_parab[t] = g_parab[t]; s_parc[t] = g_parc[t]; }
    if (t < 8) s_hld2[t] = g_hld2[t];
    int ident = g_ident;
    __syncthreads();

    int cp = t & 7;                       // fast dim -> coalesced stores, contiguous LDS
    int n  = blockIdx.x * 32 + (t >> 3);  // 32 points per block
    int nc = (n < N) ? n : (N - 1);       // clamp loads; store predicated

    const float HALF_DIM_LOG2PI = 14.7030165f;   // 0.5 * 16 * log(2*pi)
    const u64 ONE2 = pk2(1.0f, 1.0f);
    const ulonglong2* dp = &s_negD[cp];

    u64 s[16];
    u64 e0 = 0ull, e1 = 0ull;

    // ---- layer 0: s = z - z0_0 (z LDG broadcast across the 8 cp lanes) ----
    {
        const float4* zr = (const float4*)(z + (size_t)nc * DIMN);
        float4 q0 = __ldg(zr), q1 = __ldg(zr + 1), q2 = __ldg(zr + 2), q3 = __ldg(zr + 3);
        float zf[16] = { q0.x, q0.y, q0.z, q0.w, q1.x, q1.y, q1.z, q1.w,
                         q2.x, q2.y, q2.z, q2.w, q3.x, q3.y, q3.z, q3.w };
        #pragma unroll
        for (int j = 0; j < 8; j++) {
            ulonglong2 dd = dp[j * 8];
            u64 za = pk2(zf[2 * j],     zf[2 * j]);
            u64 zb = pk2(zf[2 * j + 1], zf[2 * j + 1]);
            s[2 * j]     = add2(za, dd.x);
            s[2 * j + 1] = add2(zb, dd.y);
            e0 = ffma2(s[2 * j],     s[2 * j],     e0);
            e1 = ffma2(s[2 * j + 1], s[2 * j + 1], e1);
        }
    }

    u64 P1p = ONE2, P2p = ONE2, f1p;

    // ---- layers 1..5: prefetch layer-l deltas, tail(l-1) over them, update ----
    #pragma unroll
    for (int l = 1; l < LL; l++) {
        const ulonglong2* dl = dp + l * 64;
        ulonglong2 p0 = dl[0], p1 = dl[8], p2 = dl[16], p3 = dl[24];
        ulonglong2 pab = s_parab[(l - 1) * 8 + cp];
        u64 abp = s_parc[(l - 1) * 8 + cp];

        f1p = tail_step(e0, e1, pab, abp, P1p, P2p);

        e0 = 0ull; e1 = 0ull;
        s[0] = ffma2(f1p, s[0], p0.x); s[1] = ffma2(f1p, s[1], p0.y);
        e0 = ffma2(s[0], s[0], e0);    e1 = ffma2(s[1], s[1], e1);
        s[2] = ffma2(f1p, s[2], p1.x); s[3] = ffma2(f1p, s[3], p1.y);
        e0 = ffma2(s[2], s[2], e0);    e1 = ffma2(s[3], s[3], e1);
        s[4] = ffma2(f1p, s[4], p2.x); s[5] = ffma2(f1p, s[5], p2.y);
        e0 = ffma2(s[4], s[4], e0);    e1 = ffma2(s[5], s[5], e1);
        s[6] = ffma2(f1p, s[6], p3.x); s[7] = ffma2(f1p, s[7], p3.y);
        e0 = ffma2(s[6], s[6], e0);    e1 = ffma2(s[7], s[7], e1);
        #pragma unroll
        for (int j = 4; j < 8; j++) {
            ulonglong2 dd = dl[j * 8];
            s[2 * j]     = ffma2(f1p, s[2 * j],     dd.x);
            s[2 * j + 1] = ffma2(f1p, s[2 * j + 1], dd.y);
            e0 = ffma2(s[2 * j],     s[2 * j],     e0);
            e1 = ffma2(s[2 * j + 1], s[2 * j + 1], e1);
        }
    }

    // ---- final: prefetch m5, tail(5), then q = |f1*s + m5|^2 ----
    const ulonglong2* mp = &s_m5[cp];
    ulonglong2 m0 = mp[0], m1 = mp[8], m2 = mp[16], m3 = mp[24];
    ulonglong2 pab5 = s_parab[5 * 8 + cp];
    u64 abp5 = s_parc[5 * 8 + cp];

    f1p = tail_step(e0, e1, pab5, abp5, P1p, P2p);

    float qA, qB;
    if (ident) {
        u64 a0 = 0ull, a1 = 0ull;
        u64 dx, dy;
        dx = ffma2(f1p, s[0], m0.x); dy = ffma2(f1p, s[1], m0.y);
        a0 = ffma2(dx, dx, a0);      a1 = ffma2(dy, dy, a1);
        dx = ffma2(f1p, s[2], m1.x); dy = ffma2(f1p, s[3], m1.y);
        a0 = ffma2(dx, dx, a0);      a1 = ffma2(dy, dy, a1);
        dx = ffma2(f1p, s[4], m2.x); dy = ffma2(f1p, s[5], m2.y);
        a0 = ffma2(dx, dx, a0);      a1 = ffma2(dy, dy, a1);
        dx = ffma2(f1p, s[6], m3.x); dy = ffma2(f1p, s[7], m3.y);
        a0 = ffma2(dx, dx, a0);      a1 = ffma2(dy, dy, a1);
        #pragma unroll
        for (int j = 4; j < 8; j++) {
            ulonglong2 mm = mp[j * 8];
            dx = ffma2(f1p, s[2 * j],     mm.x);
            dy = ffma2(f1p, s[2 * j + 1], mm.y);
            a0 = ffma2(dx, dx, a0);
            a1 = ffma2(dy, dy, a1);
        }
        u64 qp = add2(a0, a1);
        up2(qA, qB, qp);
    } else {
        // cold path: triangular solve with Linv from GLOBAL (perf irrelevant)
        float drA[DIMN], drB[DIMN];
        #pragma unroll
        for (int j = 0; j < 8; j++) {
            ulonglong2 mm = mp[j * 8];
            u64 dx = ffma2(f1p, s[2 * j],     mm.x);
            u64 dy = ffma2(f1p, s[2 * j + 1], mm.y);
            up2(drA[2 * j],     drB[2 * j],     dx);
            up2(drA[2 * j + 1], drB[2 * j + 1], dy);
        }
        qA = 0.0f; qB = 0.0f;
        const float* LpA = &g_Linv[2 * cp * DIMN * DIMN];
        const float* LpB = LpA + DIMN * DIMN;
        #pragma unroll 1
        for (int j = 0; j < DIMN; j++) {
            float sa = 0.0f, sb = 0.0f;
            #pragma unroll 1
            for (int i = 0; i <= j; i++) {
                sa = fmaf(LpA[j * DIMN + i], drA[i], sa);
                sb = fmaf(LpB[j * DIMN + i], drB[i], sb);
            }
            qA = fmaf(sa, sa, qA);
            qB = fmaf(sb, sb, qB);
        }
    }

    // log_det_jac total = log(P1^15 * P2), packed pow15
    u64 p2  = mul2(P1p, P1p);
    u64 p4  = mul2(p2, p2);
    u64 p8  = mul2(p4, p4);
    u64 g   = mul2(mul2(mul2(p8, p4), mul2(p2, P1p)), P2p);
    float gA, gB; up2(gA, gB, g);
    float hldA, hldB; up2(hldA, hldB, s_hld2[cp]);
    float vA = fmaf(-0.5f, qA, -HALF_DIM_LOG2PI) - hldA + __logf(gA);
    float vB = fmaf(-0.5f, qB, -HALF_DIM_LOG2PI) - hldB + __logf(gB);
    if (vA != vA) vA = __int_as_float(0xff800000);  // NaN -> -inf
    if (vB != vB) vB = __int_as_float(0xff800000);

    if (n < N)
        *(float2*)(out + (size_t)n * CC + 2 * cp) = make_float2(vA, vB);
}

// ---------------- launch ----------------
extern "C" void kernel_launch(void* const* d_in, const int* in_sizes, int n_in,
                              void* d_out, int out_size) {
    const float* z    = (const float*)d_in[0];
    const float* z0   = (const float*)d_in[1];
    const float* la   = (const float*)d_in[2];
    const float* be   = (const float*)d_in[3];
    const float* mean = (const float*)d_in[4];
    const float* cov  = (const float*)d_in[5];
    float* out = (float*)d_out;

    int N = in_sizes[0] / DIMN;

    setup_kernel<<<1, 256>>>(la, be, z0, mean, cov);
    int blocks = (N + 31) / 32;   // 32 points per block, 8 cp-threads per point
    density_kernel<<<blocks, 256>>>(z, out, N);
}

// round 15
// speedup vs baseline: 1.1051x; 1.1051x over previous
#include <cuda_runtime.h>
#include <math.h>

#define CC   16
#define DIMN 16
#define LL   6

typedef unsigned long long u64;

// ---------------- device-global precomputed params ----------------
// Deltas, cp-INNERMOST layout: entry (l, j, cp) holds dims {2j,2j+1} for c0=2cp, c1=2cp+1:
//   .x = ( -D_l[c0][2j],   -D_l[c1][2j]   )
//   .y = ( -D_l[c0][2j+1], -D_l[c1][2j+1] )   where -D_0 = -z0_0, -D_l = z0_{l-1}-z0_l
__device__ ulonglong2 g_negD2[LL * 8 * 8];   // index l*64 + j*8 + cp
__device__ ulonglong2 g_m52[8 * 8];          // (z0_5 - mean), index j*8 + cp
__device__ ulonglong2 g_parab[LL * 8];       // {(a_c0,a_c1), (b_c0,b_c1)}, index l*8+cp
__device__ u64        g_parc[LL * 8];        // (a*b) pair
__device__ u64        g_hld2[8];             // half_logdet pair
__device__ float      g_hld[CC];
__device__ float      g_Linv[CC * DIMN * DIMN];
__device__ int        g_ident;

// ---------------- f32x2 packed helpers (sm_103a) -------------------
__device__ __forceinline__ u64 pk2(float lo, float hi) {
    u64 r; asm("mov.b64 %0, {%1, %2};" : "=l"(r) : "f"(lo), "f"(hi)); return r;
}
__device__ __forceinline__ void up2(float& lo, float& hi, u64 v) {
    asm("mov.b64 {%0, %1}, %2;" : "=f"(lo), "=f"(hi) : "l"(v));
}
__device__ __forceinline__ u64 ffma2(u64 a, u64 b, u64 c) {
    u64 d; asm("fma.rn.f32x2 %0, %1, %2, %3;" : "=l"(d) : "l"(a), "l"(b), "l"(c)); return d;
}
__device__ __forceinline__ u64 add2(u64 a, u64 b) {
    u64 d; asm("add.rn.f32x2 %0, %1, %2;" : "=l"(d) : "l"(a), "l"(b)); return d;
}
__device__ __forceinline__ u64 mul2(u64 a, u64 b) {
    u64 d; asm("mul.rn.f32x2 %0, %1, %2;" : "=l"(d) : "l"(a), "l"(b)); return d;
}
__device__ __forceinline__ float fast_sqrt(float x) {
    float r; asm("sqrt.approx.f32 %0, %1;" : "=f"(r) : "f"(x)); return r;
}
__device__ __forceinline__ float fast_rcp(float x) {
    float r; asm("rcp.approx.f32 %0, %1;" : "=f"(r) : "f"(x)); return r;
}

// per-layer scalar tail: (e0+e1) -> r -> h -> f1,f2; updates P1,P2; returns f1 pair
__device__ __forceinline__ u64 tail_step(u64 e0, u64 e1, ulonglong2 pab, u64 abp,
                                         u64& P1p, u64& P2p) {
    const u64 ONE2 = pk2(1.0f, 1.0f);
    u64 r2p = add2(e0, e1);
    float rA, rB; up2(rA, rB, r2p);
    u64 rp = pk2(fast_sqrt(rA), fast_sqrt(rB));
    u64 up = add2(pab.x, rp);                 // alpha + r
    float uA, uB; up2(uA, uB, up);
    u64 hp = pk2(fast_rcp(uA), fast_rcp(uB));
    u64 f1p = ffma2(pab.y, hp, ONE2);         // 1 + beta*h
    u64 f2p = ffma2(abp, mul2(hp, hp), ONE2); // 1 + alpha*beta*h^2
    P1p = mul2(P1p, f1p);
    P2p = mul2(P2p, f2p);
    return f1p;
}

// ---------------- setup kernel (1 block) ----------------
__global__ void setup_kernel(const float* __restrict__ la, const float* __restrict__ be,
                             const float* __restrict__ z0, const float* __restrict__ mean,
                             const float* __restrict__ cov) {
    __shared__ int s_bad;
    int t = threadIdx.x;
    if (t == 0) s_bad = 0;
    __syncthreads();

    // packed params per (layer, c-pair)
    for (int i = t; i < LL * 8; i += 256) {
        int l = i / 8, cp = i % 8;
        int c0 = 2 * cp, c1 = c0 + 1;
        float a0 = expf(la[l * CC + c0]), a1 = expf(la[l * CC + c1]);
        float b0 = be[l * CC + c0],       b1 = be[l * CC + c1];
        ulonglong2 v; v.x = pk2(a0, a1); v.y = pk2(b0, b1);
        g_parab[i] = v;
        g_parc[i]  = pk2(a0 * b0, a1 * b1);
    }
    // layer deltas, cp-innermost: index l*64 + j*8 + cp
    for (int i = t; i < LL * 8 * 8; i += 256) {
        int l = i / 64, rem = i % 64, j = rem / 8, cp = rem % 8;
        int c0 = 2 * cp, c1 = c0 + 1;
        int b0 = (l * CC + c0) * DIMN + 2 * j;
        int b1 = (l * CC + c1) * DIMN + 2 * j;
        float x0 = -z0[b0], y0 = -z0[b0 + 1];
        float x1 = -z0[b1], y1 = -z0[b1 + 1];
        if (l > 0) {
            int p0 = ((l - 1) * CC + c0) * DIMN + 2 * j;
            int p1 = ((l - 1) * CC + c1) * DIMN + 2 * j;
            x0 += z0[p0]; y0 += z0[p0 + 1];
            x1 += z0[p1]; y1 += z0[p1 + 1];
        }
        ulonglong2 v; v.x = pk2(x0, x1); v.y = pk2(y0, y1);
        g_negD2[i] = v;
    }
    // final offset: z0_5 - mean, cp-innermost: index j*8 + cp
    for (int i = t; i < 8 * 8; i += 256) {
        int j = i / 8, cp = i % 8;
        int c0 = 2 * cp, c1 = c0 + 1;
        int b0 = (5 * CC + c0) * DIMN + 2 * j;
        int b1 = (5 * CC + c1) * DIMN + 2 * j;
        int m0 = c0 * DIMN + 2 * j, m1 = c1 * DIMN + 2 * j;
        ulonglong2 v;
        v.x = pk2(z0[b0]     - mean[m0],     z0[b1]     - mean[m1]);
        v.y = pk2(z0[b0 + 1] - mean[m0 + 1], z0[b1 + 1] - mean[m1 + 1]);
        g_m52[i] = v;
    }

    // cov identity check, vectorized (1024 float4, 4 per thread)
    int bad = 0;
    const float4* cv4 = (const float4*)cov;
    for (int i = t; i < CC * DIMN * DIMN / 4; i += 256) {
        float4 v = cv4[i];
        int base = i * 4;
        int r0 = base % (DIMN * DIMN);
        float e0 = ((r0 % (DIMN + 1)) == 0) ? 1.0f : 0.0f;
        float e1 = (((r0 + 1) % (DIMN + 1)) == 0) ? 1.0f : 0.0f;
        float e2 = (((r0 + 2) % (DIMN + 1)) == 0) ? 1.0f : 0.0f;
        float e3 = (((r0 + 3) % (DIMN + 1)) == 0) ? 1.0f : 0.0f;
        if (v.x != e0 || v.y != e1 || v.z != e2 || v.w != e3) bad = 1;
    }
    if (bad) atomicOr(&s_bad, 1);
    __syncthreads();
    int id = (s_bad == 0) ? 1 : 0;
    if (t == 0) g_ident = id;

    int c = t;
    if (c < CC) {
        if (id) {
            g_hld[c] = 0.0f;
        } else {
            // general Cholesky + triangular inverse (cold path)
            float Lm[DIMN][DIMN];
            const float* A = cov + c * DIMN * DIMN;
            #pragma unroll 1
            for (int j = 0; j < DIMN; j++) {
                float s = A[j * DIMN + j];
                #pragma unroll 1
                for (int k = 0; k < j; k++) s -= Lm[j][k] * Lm[j][k];
                float d = sqrtf(s);
                Lm[j][j] = d;
                float inv = 1.0f / d;
                #pragma unroll 1
                for (int i = j + 1; i < DIMN; i++) {
                    float s2 = A[i * DIMN + j];
                    #pragma unroll 1
                    for (int k = 0; k < j; k++) s2 -= Lm[i][k] * Lm[j][k];
                    Lm[i][j] = s2 * inv;
                }
            }
            float hld = 0.0f;
            #pragma unroll 1
            for (int j = 0; j < DIMN; j++) hld += logf(Lm[j][j]);
            g_hld[c] = hld;

            float Li[DIMN][DIMN];
            #pragma unroll 1
            for (int j = 0; j < DIMN; j++) {
                for (int i = 0; i < DIMN; i++) Li[i][j] = 0.0f;
                Li[j][j] = 1.0f / Lm[j][j];
                #pragma unroll 1
                for (int i = j + 1; i < DIMN; i++) {
                    float s3 = 0.0f;
                    #pragma unroll 1
                    for (int k = j; k < i; k++) s3 += Lm[i][k] * Li[k][j];
                    Li[i][j] = -s3 / Lm[i][i];
                }
            }
            for (int i = 0; i < DIMN; i++)
                for (int j = 0; j < DIMN; j++)
                    g_Linv[(c * DIMN + i) * DIMN + j] = Li[i][j];
        }
    }
    __syncthreads();
    if (t < 8) g_hld2[t] = pk2(g_hld[2 * t], g_hld[2 * t + 1]);
}

// ---------------- main density kernel: 1 thread = 2 points, shared table loads ----------------
__global__ void __launch_bounds__(128, 5)
density_kernel(const float* __restrict__ z, float* __restrict__ out, int N)
{
    __shared__ ulonglong2 s_negD[LL * 8 * 8];     // 6 KB, index l*64 + j*8 + cp
    __shared__ ulonglong2 s_m5[8 * 8];            // 1 KB, index j*8 + cp
    __shared__ ulonglong2 s_parab[LL * 8];        // 768 B
    __shared__ u64        s_parc[LL * 8];         // 384 B
    __shared__ u64        s_hld2[8];

    int t = threadIdx.x;
    for (int i = t; i < LL * 8 * 8; i += 128) s_negD[i] = g_negD2[i];
    if (t < 8 * 8) s_m5[t] = g_m52[t];
    if (t < LL * 8) { s_parab[t] = g_parab[t]; s_parc[t] = g_parc[t]; }
    if (t < 8) s_hld2[t] = g_hld2[t];
    int ident = g_ident;
    __syncthreads();

    int n0 = blockIdx.x * 256 + t;      // point A
    int n1 = n0 + 128;                  // point B
    int nA = (n0 < N) ? n0 : (N - 1);   // clamp loads; stores predicated
    int nB = (n1 < N) ? n1 : (N - 1);
    const float4* zrA = (const float4*)(z + (size_t)nA * DIMN);
    const float4* zrB = (const float4*)(z + (size_t)nB * DIMN);

    const float HALF_DIM_LOG2PI = 14.7030165f;   // 0.5 * 16 * log(2*pi)
    const u64 ONE2 = pk2(1.0f, 1.0f);

    #pragma unroll 1
    for (int cp = 0; cp < 8; cp++) {
        const ulonglong2* dp = &s_negD[cp];

        u64 sA[16], sB[16];
        u64 e0A = 0ull, e1A = 0ull, e0B = 0ull, e1B = 0ull;

        // ---- layer 0: s = z - z0_0 (z from L1, same addresses every cp) ----
        {
            float4 qa0 = __ldg(zrA),     qa1 = __ldg(zrA + 1),
                   qa2 = __ldg(zrA + 2), qa3 = __ldg(zrA + 3);
            float4 qb0 = __ldg(zrB),     qb1 = __ldg(zrB + 1),
                   qb2 = __ldg(zrB + 2), qb3 = __ldg(zrB + 3);
            float zfA[16] = { qa0.x, qa0.y, qa0.z, qa0.w, qa1.x, qa1.y, qa1.z, qa1.w,
                              qa2.x, qa2.y, qa2.z, qa2.w, qa3.x, qa3.y, qa3.z, qa3.w };
            float zfB[16] = { qb0.x, qb0.y, qb0.z, qb0.w, qb1.x, qb1.y, qb1.z, qb1.w,
                              qb2.x, qb2.y, qb2.z, qb2.w, qb3.x, qb3.y, qb3.z, qb3.w };
            #pragma unroll
            for (int j = 0; j < 8; j++) {
                ulonglong2 dd = dp[j * 8];          // shared by both points
                sA[2 * j]     = add2(pk2(zfA[2 * j],     zfA[2 * j]),     dd.x);
                sA[2 * j + 1] = add2(pk2(zfA[2 * j + 1], zfA[2 * j + 1]), dd.y);
                sB[2 * j]     = add2(pk2(zfB[2 * j],     zfB[2 * j]),     dd.x);
                sB[2 * j + 1] = add2(pk2(zfB[2 * j + 1], zfB[2 * j + 1]), dd.y);
                e0A = ffma2(sA[2 * j],     sA[2 * j],     e0A);
                e1A = ffma2(sA[2 * j + 1], sA[2 * j + 1], e1A);
                e0B = ffma2(sB[2 * j],     sB[2 * j],     e0B);
                e1B = ffma2(sB[2 * j + 1], sB[2 * j + 1], e1B);
            }
        }

        u64 P1A = ONE2, P2A = ONE2, P1B = ONE2, P2B = ONE2, f1A, f1B;

        // ---- layers 1..5: one set of table loads feeds both chains ----
        #pragma unroll
        for (int l = 1; l < LL; l++) {
            const ulonglong2* dl = dp + l * 64;
            ulonglong2 p0 = dl[0], p1 = dl[8];       // shallow prefetch over tails
            ulonglong2 pab = s_parab[(l - 1) * 8 + cp];
            u64 abp = s_parc[(l - 1) * 8 + cp];

            f1A = tail_step(e0A, e1A, pab, abp, P1A, P2A);
            f1B = tail_step(e0B, e1B, pab, abp, P1B, P2B);

            e0A = 0ull; e1A = 0ull; e0B = 0ull; e1B = 0ull;
            sA[0] = ffma2(f1A, sA[0], p0.x); sA[1] = ffma2(f1A, sA[1], p0.y);
            sB[0] = ffma2(f1B, sB[0], p0.x); sB[1] = ffma2(f1B, sB[1], p0.y);
            e0A = ffma2(sA[0], sA[0], e0A);  e1A = ffma2(sA[1], sA[1], e1A);
            e0B = ffma2(sB[0], sB[0], e0B);  e1B = ffma2(sB[1], sB[1], e1B);
            sA[2] = ffma2(f1A, sA[2], p1.x); sA[3] = ffma2(f1A, sA[3], p1.y);
            sB[2] = ffma2(f1B, sB[2], p1.x); sB[3] = ffma2(f1B, sB[3], p1.y);
            e0A = ffma2(sA[2], sA[2], e0A);  e1A = ffma2(sA[3], sA[3], e1A);
            e0B = ffma2(sB[2], sB[2], e0B);  e1B = ffma2(sB[3], sB[3], e1B);
            #pragma unroll
            for (int j = 2; j < 8; j++) {
                ulonglong2 dd = dl[j * 8];
                sA[2 * j]     = ffma2(f1A, sA[2 * j],     dd.x);
                sA[2 * j + 1] = ffma2(f1A, sA[2 * j + 1], dd.y);
                sB[2 * j]     = ffma2(f1B, sB[2 * j],     dd.x);
                sB[2 * j + 1] = ffma2(f1B, sB[2 * j + 1], dd.y);
                e0A = ffma2(sA[2 * j],     sA[2 * j],     e0A);
                e1A = ffma2(sA[2 * j + 1], sA[2 * j + 1], e1A);
                e0B = ffma2(sB[2 * j],     sB[2 * j],     e0B);
                e1B = ffma2(sB[2 * j + 1], sB[2 * j + 1], e1B);
            }
        }

        // ---- final: tails, then q = |f1*s + m5|^2 for both chains ----
        const ulonglong2* mp = &s_m5[cp];
        ulonglong2 pab5 = s_parab[5 * 8 + cp];
        u64 abp5 = s_parc[5 * 8 + cp];

        f1A = tail_step(e0A, e1A, pab5, abp5, P1A, P2A);
        f1B = tail_step(e0B, e1B, pab5, abp5, P1B, P2B);

        float qA0, qA1, qB0, qB1;
        if (ident) {
            u64 aa0 = 0ull, aa1 = 0ull, bb0 = 0ull, bb1 = 0ull;
            #pragma unroll
            for (int j = 0; j < 8; j++) {
                ulonglong2 mm = mp[j * 8];
                u64 dxA = ffma2(f1A, sA[2 * j],     mm.x);
                u64 dyA = ffma2(f1A, sA[2 * j + 1], mm.y);
                u64 dxB = ffma2(f1B, sB[2 * j],     mm.x);
                u64 dyB = ffma2(f1B, sB[2 * j + 1], mm.y);
                aa0 = ffma2(dxA, dxA, aa0); aa1 = ffma2(dyA, dyA, aa1);
                bb0 = ffma2(dxB, dxB, bb0); bb1 = ffma2(dyB, dyB, bb1);
            }
            u64 qpA = add2(aa0, aa1);
            u64 qpB = add2(bb0, bb1);
            up2(qA0, qA1, qpA);
            up2(qB0, qB1, qpB);
        } else {
            // cold path: triangular solve with Linv from GLOBAL (perf irrelevant)
            float drA0[DIMN], drA1[DIMN], drB0[DIMN], drB1[DIMN];
            #pragma unroll
            for (int j = 0; j < 8; j++) {
                ulonglong2 mm = mp[j * 8];
                u64 dxA = ffma2(f1A, sA[2 * j],     mm.x);
                u64 dyA = ffma2(f1A, sA[2 * j + 1], mm.y);
                u64 dxB = ffma2(f1B, sB[2 * j],     mm.x);
                u64 dyB = ffma2(f1B, sB[2 * j + 1], mm.y);
                up2(drA0[2 * j],     drA1[2 * j],     dxA);
                up2(drA0[2 * j + 1], drA1[2 * j + 1], dyA);
                up2(drB0[2 * j],     drB1[2 * j],     dxB);
                up2(drB0[2 * j + 1], drB1[2 * j + 1], dyB);
            }
            qA0 = qA1 = qB0 = qB1 = 0.0f;
            const float* Lp0 = &g_Linv[2 * cp * DIMN * DIMN];
            const float* Lp1 = Lp0 + DIMN * DIMN;
            #pragma unroll 1
            for (int j = 0; j < DIMN; j++) {
                float sa0 = 0.0f, sa1 = 0.0f, sb0 = 0.0f, sb1 = 0.0f;
                #pragma unroll 1
                for (int i = 0; i <= j; i++) {
                    float l0 = Lp0[j * DIMN + i], l1 = Lp1[j * DIMN + i];
                    sa0 = fmaf(l0, drA0[i], sa0);
                    sa1 = fmaf(l1, drA1[i], sa1);
                    sb0 = fmaf(l0, drB0[i], sb0);
                    sb1 = fmaf(l1, drB1[i], sb1);
                }
                qA0 = fmaf(sa0, sa0, qA0); qA1 = fmaf(sa1, sa1, qA1);
                qB0 = fmaf(sb0, sb0, qB0); qB1 = fmaf(sb1, sb1, qB1);
            }
        }

        // log_det_jac total = log(P1^15 * P2), packed pow15; write both points
        float hld0, hld1; up2(hld0, hld1, s_hld2[cp]);
        {
            u64 p2  = mul2(P1A, P1A);
            u64 p4  = mul2(p2, p2);
            u64 p8  = mul2(p4, p4);
            u64 g   = mul2(mul2(mul2(p8, p4), mul2(p2, P1A)), P2A);
            float g0, g1; up2(g0, g1, g);
            float v0 = fmaf(-0.5f, qA0, -HALF_DIM_LOG2PI) - hld0 + __logf(g0);
            float v1 = fmaf(-0.5f, qA1, -HALF_DIM_LOG2PI) - hld1 + __logf(g1);
            if (v0 != v0) v0 = __int_as_float(0xff800000);
            if (v1 != v1) v1 = __int_as_float(0xff800000);
            if (n0 < N)
                *(float2*)(out + (size_t)n0 * CC + 2 * cp) = make_float2(v0, v1);
        }
        {
            u64 p2  = mul2(P1B, P1B);
            u64 p4  = mul2(p2, p2);
            u64 p8  = mul2(p4, p4);
            u64 g   = mul2(mul2(mul2(p8, p4), mul2(p2, P1B)), P2B);
            float g0, g1; up2(g0, g1, g);
            float v0 = fmaf(-0.5f, qB0, -HALF_DIM_LOG2PI) - hld0 + __logf(g0);
            float v1 = fmaf(-0.5f, qB1, -HALF_DIM_LOG2PI) - hld1 + __logf(g1);
            if (v0 != v0) v0 = __int_as_float(0xff800000);
            if (v1 != v1) v1 = __int_as_float(0xff800000);
            if (n1 < N)
                *(float2*)(out + (size_t)n1 * CC + 2 * cp) = make_float2(v0, v1);
        }
    }
}

// ---------------- launch ----------------
extern "C" void kernel_launch(void* const* d_in, const int* in_sizes, int n_in,
                              void* d_out, int out_size) {
    const float* z    = (const float*)d_in[0];
    const float* z0   = (const float*)d_in[1];
    const float* la   = (const float*)d_in[2];
    const float* be   = (const float*)d_in[3];
    const float* mean = (const float*)d_in[4];
    const float* cov  = (const float*)d_in[5];
    float* out = (float*)d_out;

    int N = in_sizes[0] / DIMN;

    setup_kernel<<<1, 256>>>(la, be, z0, mean, cov);
    int blocks = (N + 255) / 256;   // 2 points per thread, 128 threads per block
    density_kernel<<<blocks, 128>>>(z, out, N);
}

// round 16
// speedup vs baseline: 1.1643x; 1.0535x over previous
#include <cuda_runtime.h>
#include <math.h>

#define CC   16
#define DIMN 16
#define LL   6

typedef unsigned long long u64;

// ---------------- device-global precomputed params ----------------
// Deltas, cp-INNERMOST layout: entry (l, j, cp) holds dims {2j,2j+1} for c0=2cp, c1=2cp+1:
//   .x = ( -D_l[c0][2j],   -D_l[c1][2j]   )
//   .y = ( -D_l[c0][2j+1], -D_l[c1][2j+1] )   where -D_0 = -z0_0, -D_l = z0_{l-1}-z0_l
__device__ ulonglong2 g_negD2[LL * 8 * 8];   // index l*64 + j*8 + cp
__device__ ulonglong2 g_m52[8 * 8];          // (z0_5 - mean), index j*8 + cp
__device__ ulonglong2 g_parab[LL * 8];       // {(a_c0,a_c1), (b_c0,b_c1)}, index l*8+cp
__device__ u64        g_parc[LL * 8];        // (a*b) pair
__device__ u64        g_d2[LL * 8];          // (|D_l[c0]|^2, |D_l[c1]|^2) pair
__device__ u64        g_m5sq[8];             // (|m5[c0]|^2, |m5[c1]|^2) pair
__device__ u64        g_hld2[8];             // half_logdet pair
__device__ float      g_hld[CC];
__device__ float      g_Linv[CC * DIMN * DIMN];
__device__ int        g_ident;

// ---------------- f32x2 packed helpers (sm_103a) -------------------
__device__ __forceinline__ u64 pk2(float lo, float hi) {
    u64 r; asm("mov.b64 %0, {%1, %2};" : "=l"(r) : "f"(lo), "f"(hi)); return r;
}
__device__ __forceinline__ void up2(float& lo, float& hi, u64 v) {
    asm("mov.b64 {%0, %1}, %2;" : "=f"(lo), "=f"(hi) : "l"(v));
}
__device__ __forceinline__ u64 ffma2(u64 a, u64 b, u64 c) {
    u64 d; asm("fma.rn.f32x2 %0, %1, %2, %3;" : "=l"(d) : "l"(a), "l"(b), "l"(c)); return d;
}
__device__ __forceinline__ u64 add2(u64 a, u64 b) {
    u64 d; asm("add.rn.f32x2 %0, %1, %2;" : "=l"(d) : "l"(a), "l"(b)); return d;
}
__device__ __forceinline__ u64 mul2(u64 a, u64 b) {
    u64 d; asm("mul.rn.f32x2 %0, %1, %2;" : "=l"(d) : "l"(a), "l"(b)); return d;
}
__device__ __forceinline__ float fast_sqrt(float x) {
    float r; asm("sqrt.approx.f32 %0, %1;" : "=f"(r) : "f"(x)); return r;
}
__device__ __forceinline__ float fast_rcp(float x) {
    float r; asm("rcp.approx.f32 %0, %1;" : "=f"(r) : "f"(x)); return r;
}

// scalar tail from packed r^2: r -> h -> f1,f2; updates P1,P2; returns f1 pair
__device__ __forceinline__ u64 tail2(u64 r2p, ulonglong2 pab, u64 abp,
                                     u64& P1p, u64& P2p) {
    const u64 ONE2 = pk2(1.0f, 1.0f);
    float rA, rB; up2(rA, rB, r2p);
    rA = fast_sqrt(fmaxf(rA, 0.0f));          // clamp: recurrence rounding guard
    rB = fast_sqrt(fmaxf(rB, 0.0f));
    u64 rp = pk2(rA, rB);
    u64 up = add2(pab.x, rp);                 // alpha + r
    float uA, uB; up2(uA, uB, up);
    u64 hp = pk2(fast_rcp(uA), fast_rcp(uB));
    u64 f1p = ffma2(pab.y, hp, ONE2);         // 1 + beta*h
    u64 f2p = ffma2(abp, mul2(hp, hp), ONE2); // 1 + alpha*beta*h^2
    P1p = mul2(P1p, f1p);
    P2p = mul2(P2p, f2p);
    return f1p;
}

// ---------------- setup kernel (1 block) ----------------
__global__ void setup_kernel(const float* __restrict__ la, const float* __restrict__ be,
                             const float* __restrict__ z0, const float* __restrict__ mean,
                             const float* __restrict__ cov) {
    __shared__ int s_bad;
    int t = threadIdx.x;
    if (t == 0) s_bad = 0;
    __syncthreads();

    // packed params per (layer, c-pair)
    for (int i = t; i < LL * 8; i += 256) {
        int l = i / 8, cp = i % 8;
        int c0 = 2 * cp, c1 = c0 + 1;
        float a0 = expf(la[l * CC + c0]), a1 = expf(la[l * CC + c1]);
        float b0 = be[l * CC + c0],       b1 = be[l * CC + c1];
        ulonglong2 v; v.x = pk2(a0, a1); v.y = pk2(b0, b1);
        g_parab[i] = v;
        g_parc[i]  = pk2(a0 * b0, a1 * b1);
    }
    // layer deltas, cp-innermost; plus |D|^2 pair table
    for (int i = t; i < LL * 8 * 8; i += 256) {
        int l = i / 64, rem = i % 64, j = rem / 8, cp = rem % 8;
        int c0 = 2 * cp, c1 = c0 + 1;
        int b0 = (l * CC + c0) * DIMN + 2 * j;
        int b1 = (l * CC + c1) * DIMN + 2 * j;
        float x0 = -z0[b0], y0 = -z0[b0 + 1];
        float x1 = -z0[b1], y1 = -z0[b1 + 1];
        if (l > 0) {
            int p0 = ((l - 1) * CC + c0) * DIMN + 2 * j;
            int p1 = ((l - 1) * CC + c1) * DIMN + 2 * j;
            x0 += z0[p0]; y0 += z0[p0 + 1];
            x1 += z0[p1]; y1 += z0[p1 + 1];
        }
        ulonglong2 v; v.x = pk2(x0, x1); v.y = pk2(y0, y1);
        g_negD2[i] = v;
    }
    // |D_l|^2 pairs (all layers; used for l>=1)
    for (int i = t; i < LL * 8; i += 256) {
        int l = i / 8, cp = i % 8;
        int c0 = 2 * cp, c1 = c0 + 1;
        float s0 = 0.0f, s1 = 0.0f;
        for (int d = 0; d < DIMN; d++) {
            float v0 = -z0[(l * CC + c0) * DIMN + d];
            float v1 = -z0[(l * CC + c1) * DIMN + d];
            if (l > 0) {
                v0 += z0[((l - 1) * CC + c0) * DIMN + d];
                v1 += z0[((l - 1) * CC + c1) * DIMN + d];
            }
            s0 += v0 * v0; s1 += v1 * v1;
        }
        g_d2[i] = pk2(s0, s1);
    }
    // final offset: z0_5 - mean; plus |m5|^2 pairs
    for (int i = t; i < 8 * 8; i += 256) {
        int j = i / 8, cp = i % 8;
        int c0 = 2 * cp, c1 = c0 + 1;
        int b0 = (5 * CC + c0) * DIMN + 2 * j;
        int b1 = (5 * CC + c1) * DIMN + 2 * j;
        int m0 = c0 * DIMN + 2 * j, m1 = c1 * DIMN + 2 * j;
        ulonglong2 v;
        v.x = pk2(z0[b0]     - mean[m0],     z0[b1]     - mean[m1]);
        v.y = pk2(z0[b0 + 1] - mean[m0 + 1], z0[b1 + 1] - mean[m1 + 1]);
        g_m52[i] = v;
    }
    if (t < 8) {
        int c0 = 2 * t, c1 = c0 + 1;
        float s0 = 0.0f, s1 = 0.0f;
        for (int d = 0; d < DIMN; d++) {
            float v0 = z0[(5 * CC + c0) * DIMN + d] - mean[c0 * DIMN + d];
            float v1 = z0[(5 * CC + c1) * DIMN + d] - mean[c1 * DIMN + d];
            s0 += v0 * v0; s1 += v1 * v1;
        }
        g_m5sq[t] = pk2(s0, s1);
    }

    // cov identity check, vectorized (1024 float4, 4 per thread)
    int bad = 0;
    const float4* cv4 = (const float4*)cov;
    for (int i = t; i < CC * DIMN * DIMN / 4; i += 256) {
        float4 v = cv4[i];
        int base = i * 4;
        int r0 = base % (DIMN * DIMN);
        float e0 = ((r0 % (DIMN + 1)) == 0) ? 1.0f : 0.0f;
        float e1 = (((r0 + 1) % (DIMN + 1)) == 0) ? 1.0f : 0.0f;
        float e2 = (((r0 + 2) % (DIMN + 1)) == 0) ? 1.0f : 0.0f;
        float e3 = (((r0 + 3) % (DIMN + 1)) == 0) ? 1.0f : 0.0f;
        if (v.x != e0 || v.y != e1 || v.z != e2 || v.w != e3) bad = 1;
    }
    if (bad) atomicOr(&s_bad, 1);
    __syncthreads();
    int id = (s_bad == 0) ? 1 : 0;
    if (t == 0) g_ident = id;

    int c = t;
    if (c < CC) {
        if (id) {
            g_hld[c] = 0.0f;
        } else {
            // general Cholesky + triangular inverse (cold path)
            float Lm[DIMN][DIMN];
            const float* A = cov + c * DIMN * DIMN;
            #pragma unroll 1
            for (int j = 0; j < DIMN; j++) {
                float s = A[j * DIMN + j];
                #pragma unroll 1
                for (int k = 0; k < j; k++) s -= Lm[j][k] * Lm[j][k];
                float d = sqrtf(s);
                Lm[j][j] = d;
                float inv = 1.0f / d;
                #pragma unroll 1
                for (int i = j + 1; i < DIMN; i++) {
                    float s2 = A[i * DIMN + j];
                    #pragma unroll 1
                    for (int k = 0; k < j; k++) s2 -= Lm[i][k] * Lm[j][k];
                    Lm[i][j] = s2 * inv;
                }
            }
            float hld = 0.0f;
            #pragma unroll 1
            for (int j = 0; j < DIMN; j++) hld += logf(Lm[j][j]);
            g_hld[c] = hld;

            float Li[DIMN][DIMN];
            #pragma unroll 1
            for (int j = 0; j < DIMN; j++) {
                for (int i = 0; i < DIMN; i++) Li[i][j] = 0.0f;
                Li[j][j] = 1.0f / Lm[j][j];
                #pragma unroll 1
                for (int i = j + 1; i < DIMN; i++) {
                    float s3 = 0.0f;
                    #pragma unroll 1
                    for (int k = j; k < i; k++) s3 += Lm[i][k] * Li[k][j];
                    Li[i][j] = -s3 / Lm[i][i];
                }
            }
            for (int i = 0; i < DIMN; i++)
                for (int j = 0; j < DIMN; j++)
                    g_Linv[(c * DIMN + i) * DIMN + j] = Li[i][j];
        }
    }
    __syncthreads();
    if (t < 8) g_hld2[t] = pk2(g_hld[2 * t], g_hld[2 * t + 1]);
}

// ---------------- main density kernel: r^2 recurrence, dot overlapped with MUFU tail ----------------
__global__ void __launch_bounds__(128, 5)
density_kernel(const float* __restrict__ z, float* __restrict__ out, int N)
{
    __shared__ ulonglong2 s_negD[LL * 8 * 8];     // 6 KB, index l*64 + j*8 + cp
    __shared__ ulonglong2 s_m5[8 * 8];            // 1 KB, index j*8 + cp
    __shared__ ulonglong2 s_parab[LL * 8];        // 768 B
    __shared__ u64        s_parc[LL * 8];         // 384 B
    __shared__ u64        s_d2[LL * 8];           // 384 B
    __shared__ u64        s_m5sq[8];
    __shared__ u64        s_hld2[8];

    int t = threadIdx.x;
    for (int i = t; i < LL * 8 * 8; i += 128) s_negD[i] = g_negD2[i];
    if (t < 8 * 8) s_m5[t] = g_m52[t];
    if (t < LL * 8) { s_parab[t] = g_parab[t]; s_parc[t] = g_parc[t]; s_d2[t] = g_d2[t]; }
    if (t < 8) { s_hld2[t] = g_hld2[t]; s_m5sq[t] = g_m5sq[t]; }
    int ident = g_ident;
    __syncthreads();

    int n = blockIdx.x * 128 + t;
    if (n >= N) return;

    // z row as 16 scalar registers (pk2 broadcast on use in layer 0)
    const float4* zr = (const float4*)(z + (size_t)n * DIMN);
    float4 q0 = zr[0], q1 = zr[1], q2 = zr[2], q3 = zr[3];
    float zf[16] = { q0.x, q0.y, q0.z, q0.w, q1.x, q1.y, q1.z, q1.w,
                     q2.x, q2.y, q2.z, q2.w, q3.x, q3.y, q3.z, q3.w };

    const float HALF_DIM_LOG2PI = 14.7030165f;   // 0.5 * 16 * log(2*pi)
    const u64 ONE2 = pk2(1.0f, 1.0f);

    #pragma unroll 1
    for (int cp = 0; cp < 8; cp++) {
        const ulonglong2* dp = &s_negD[cp];

        u64 s[16];
        u64 r2p;

        // ---- layer 0: s = z - z0_0, r2 by direct square-accum ----
        {
            u64 e0 = 0ull, e1 = 0ull;
            #pragma unroll
            for (int j = 0; j < 8; j++) {
                ulonglong2 dd = dp[j * 8];
                s[2 * j]     = add2(pk2(zf[2 * j],     zf[2 * j]),     dd.x);
                s[2 * j + 1] = add2(pk2(zf[2 * j + 1], zf[2 * j + 1]), dd.y);
                e0 = ffma2(s[2 * j],     s[2 * j],     e0);
                e1 = ffma2(s[2 * j + 1], s[2 * j + 1], e1);
            }
            r2p = add2(e0, e1);       // (r2_c0, r2_c1)
        }

        u64 P1p = ONE2, P2p = ONE2, f1p;

        // ---- layers 1..5: dot(s_{l-1}, negD_l) overlaps tail(l-1); r2 via recurrence ----
        #pragma unroll
        for (int l = 1; l < LL; l++) {
            const ulonglong2* dl = dp + l * 64;
            // dot: independent of f1 -> issues under the MUFU tail below
            u64 t0 = 0ull, t1 = 0ull;
            #pragma unroll
            for (int j = 0; j < 8; j++) {
                ulonglong2 dd = dl[j * 8];
                t0 = ffma2(s[2 * j],     dd.x, t0);
                t1 = ffma2(s[2 * j + 1], dd.y, t1);
            }
            u64 dotp = add2(t0, t1);  // (s·negD)_c0, _c1

            f1p = tail2(r2p, s_parab[(l - 1) * 8 + cp], s_parc[(l - 1) * 8 + cp], P1p, P2p);

            // r2_l = f1^2 r2 + 2 f1 (s·negD) + |D|^2   (2 serial ffma2 after f1)
            r2p = ffma2(f1p, ffma2(f1p, r2p, add2(dotp, dotp)), s_d2[l * 8 + cp]);

            // s_l = f1 * s + negD_l
            #pragma unroll
            for (int j = 0; j < 8; j++) {
                ulonglong2 dd = dl[j * 8];
                s[2 * j]     = ffma2(f1p, s[2 * j],     dd.x);
                s[2 * j + 1] = ffma2(f1p, s[2 * j + 1], dd.y);
            }
        }

        // ---- final: dot(s5, m5) overlaps tail(5); q closed-form ----
        const ulonglong2* mp = &s_m5[cp];
        u64 t0 = 0ull, t1 = 0ull;
        #pragma unroll
        for (int j = 0; j < 8; j++) {
            ulonglong2 mm = mp[j * 8];
            t0 = ffma2(s[2 * j],     mm.x, t0);
            t1 = ffma2(s[2 * j + 1], mm.y, t1);
        }
        u64 dotm = add2(t0, t1);

        f1p = tail2(r2p, s_parab[5 * 8 + cp], s_parc[5 * 8 + cp], P1p, P2p);

        float qA, qB;
        if (ident) {
            // q = f1^2 r2 + 2 f1 (s·m5) + |m5|^2
            u64 qp = ffma2(f1p, ffma2(f1p, r2p, add2(dotm, dotm)), s_m5sq[cp]);
            up2(qA, qB, qp);
        } else {
            // cold path: explicit diff + triangular solve with Linv from GLOBAL
            float drA[DIMN], drB[DIMN];
            #pragma unroll
            for (int j = 0; j < 8; j++) {
                ulonglong2 mm = mp[j * 8];
                u64 dx = ffma2(f1p, s[2 * j],     mm.x);
                u64 dy = ffma2(f1p, s[2 * j + 1], mm.y);
                up2(drA[2 * j],     drB[2 * j],     dx);
                up2(drA[2 * j + 1], drB[2 * j + 1], dy);
            }
            qA = 0.0f; qB = 0.0f;
            const float* LpA = &g_Linv[2 * cp * DIMN * DIMN];
            const float* LpB = LpA + DIMN * DIMN;
            #pragma unroll 1
            for (int j = 0; j < DIMN; j++) {
                float sa = 0.0f, sb = 0.0f;
                #pragma unroll 1
                for (int i = 0; i <= j; i++) {
                    sa = fmaf(LpA[j * DIMN + i], drA[i], sa);
                    sb = fmaf(LpB[j * DIMN + i], drB[i], sb);
                }
                qA = fmaf(sa, sa, qA);
                qB = fmaf(sb, sb, qB);
            }
        }

        // log_det_jac total = log(P1^15 * P2), packed pow15
        u64 p2  = mul2(P1p, P1p);
        u64 p4  = mul2(p2, p2);
        u64 p8  = mul2(p4, p4);
        u64 g   = mul2(mul2(mul2(p8, p4), mul2(p2, P1p)), P2p);
        float gA, gB; up2(gA, gB, g);
        float hldA, hldB; up2(hldA, hldB, s_hld2[cp]);
        float vA = fmaf(-0.5f, qA, -HALF_DIM_LOG2PI) - hldA + __logf(gA);
        float vB = fmaf(-0.5f, qB, -HALF_DIM_LOG2PI) - hldB + __logf(gB);
        if (vA != vA) vA = __int_as_float(0xff800000);  // NaN -> -inf
        if (vB != vB) vB = __int_as_float(0xff800000);

        *(float2*)(out + (size_t)n * CC + 2 * cp) = make_float2(vA, vB);
    }
}

// ---------------- launch ----------------
extern "C" void kernel_launch(void* const* d_in, const int* in_sizes, int n_in,
                              void* d_out, int out_size) {
    const float* z    = (const float*)d_in[0];
    const float* z0   = (const float*)d_in[1];
    const float* la   = (const float*)d_in[2];
    const float* be   = (const float*)d_in[3];
    const float* mean = (const float*)d_in[4];
    const float* cov  = (const float*)d_in[5];
    float* out = (float*)d_out;

    int N = in_sizes[0] / DIMN;

    setup_kernel<<<1, 256>>>(la, be, z0, mean, cov);
    int blocks = (N + 127) / 128;
    density_kernel<<<blocks, 128>>>(z, out, N);
}

// round 17
// speedup vs baseline: 1.1981x; 1.0291x over previous
#include <cuda_runtime.h>
#include <math.h>

#define CC   16
#define DIMN 16
#define LL   6

typedef unsigned long long u64;

// ---------------- device-global precomputed params ----------------
// negD_l = -(z0_l - z0_{l-1}); negD_0 = -z0_0.  cp-innermost pair layout as before.
__device__ ulonglong2 g_negD2[LL * 8 * 8];   // index l*64 + j*8 + cp
__device__ ulonglong2 g_m52[8 * 8];          // (z0_5 - mean), index j*8 + cp
__device__ ulonglong2 g_parab[LL * 8];       // {(a_c0,a_c1), (b_c0,b_c1)}
__device__ u64        g_parc[LL * 8];        // (a*b) pair
__device__ u64        g_d2[LL * 8];          // |negD_l|^2 pair
__device__ u64        g_G[36 * 8];           // Gram: negD_k · negD_m, index (k*6+m)*8+cp (k<m used)
__device__ u64        g_Gm[LL * 8];          // negD_k · m5 pair
__device__ u64        g_m5sq[8];             // |m5|^2 pair
__device__ u64        g_hld2[8];             // half_logdet pair
__device__ float      g_hld[CC];
__device__ float      g_Linv[CC * DIMN * DIMN];
__device__ int        g_ident;

// ---------------- f32x2 packed helpers (sm_103a) -------------------
__device__ __forceinline__ u64 pk2(float lo, float hi) {
    u64 r; asm("mov.b64 %0, {%1, %2};" : "=l"(r) : "f"(lo), "f"(hi)); return r;
}
__device__ __forceinline__ void up2(float& lo, float& hi, u64 v) {
    asm("mov.b64 {%0, %1}, %2;" : "=f"(lo), "=f"(hi) : "l"(v));
}
__device__ __forceinline__ u64 ffma2(u64 a, u64 b, u64 c) {
    u64 d; asm("fma.rn.f32x2 %0, %1, %2, %3;" : "=l"(d) : "l"(a), "l"(b), "l"(c)); return d;
}
__device__ __forceinline__ u64 add2(u64 a, u64 b) {
    u64 d; asm("add.rn.f32x2 %0, %1, %2;" : "=l"(d) : "l"(a), "l"(b)); return d;
}
__device__ __forceinline__ u64 mul2(u64 a, u64 b) {
    u64 d; asm("mul.rn.f32x2 %0, %1, %2;" : "=l"(d) : "l"(a), "l"(b)); return d;
}
__device__ __forceinline__ float fast_sqrt(float x) {
    float r; asm("sqrt.approx.f32 %0, %1;" : "=f"(r) : "f"(x)); return r;
}
__device__ __forceinline__ float fast_rcp(float x) {
    float r; asm("rcp.approx.f32 %0, %1;" : "=f"(r) : "f"(x)); return r;
}

// scalar tail from packed r^2: r -> h -> f1,f2; updates P1,P2; returns f1 pair
__device__ __forceinline__ u64 tail2(u64 r2p, ulonglong2 pab, u64 abp,
                                     u64& P1p, u64& P2p) {
    const u64 ONE2 = pk2(1.0f, 1.0f);
    float rA, rB; up2(rA, rB, r2p);
    rA = fast_sqrt(fmaxf(rA, 0.0f));          // clamp: recurrence rounding guard
    rB = fast_sqrt(fmaxf(rB, 0.0f));
    u64 rp = pk2(rA, rB);
    u64 up = add2(pab.x, rp);                 // alpha + r
    float uA, uB; up2(uA, uB, up);
    u64 hp = pk2(fast_rcp(uA), fast_rcp(uB));
    u64 f1p = ffma2(pab.y, hp, ONE2);         // 1 + beta*h
    u64 f2p = ffma2(abp, mul2(hp, hp), ONE2); // 1 + alpha*beta*h^2
    P1p = mul2(P1p, f1p);
    P2p = mul2(P2p, f2p);
    return f1p;
}

// ---------------- setup kernel (1 block, 256 threads) ----------------
__global__ void setup_kernel(const float* __restrict__ la, const float* __restrict__ be,
                             const float* __restrict__ z0, const float* __restrict__ mean,
                             const float* __restrict__ cov) {
    __shared__ float s_z0[LL * CC * DIMN];   // 6 KB staging
    __shared__ float s_mean[CC * DIMN];      // 1 KB
    __shared__ int s_bad;
    int t = threadIdx.x;
    if (t == 0) s_bad = 0;
    for (int i = t; i < LL * CC * DIMN; i += 256) s_z0[i] = z0[i];
    for (int i = t; i < CC * DIMN; i += 256) s_mean[i] = mean[i];
    __syncthreads();

    // negd(l,c,d) helper via lambda on staged arrays
    auto negd = [&](int l, int c, int d) -> float {
        float v = -s_z0[(l * CC + c) * DIMN + d];
        if (l > 0) v += s_z0[((l - 1) * CC + c) * DIMN + d];
        return v;
    };
    auto m5v = [&](int c, int d) -> float {
        return s_z0[(5 * CC + c) * DIMN + d] - s_mean[c * DIMN + d];
    };

    // packed params
    for (int i = t; i < LL * 8; i += 256) {
        int l = i / 8, cp = i % 8;
        int c0 = 2 * cp, c1 = c0 + 1;
        float a0 = expf(la[l * CC + c0]), a1 = expf(la[l * CC + c1]);
        float b0 = be[l * CC + c0],       b1 = be[l * CC + c1];
        ulonglong2 v; v.x = pk2(a0, a1); v.y = pk2(b0, b1);
        g_parab[i] = v;
        g_parc[i]  = pk2(a0 * b0, a1 * b1);
    }
    // layer deltas
    for (int i = t; i < LL * 8 * 8; i += 256) {
        int l = i / 64, rem = i % 64, j = rem / 8, cp = rem % 8;
        int c0 = 2 * cp, c1 = c0 + 1;
        ulonglong2 v;
        v.x = pk2(negd(l, c0, 2 * j),     negd(l, c1, 2 * j));
        v.y = pk2(negd(l, c0, 2 * j + 1), negd(l, c1, 2 * j + 1));
        g_negD2[i] = v;
    }
    // |negD_l|^2 pairs
    for (int i = t; i < LL * 8; i += 256) {
        int l = i / 8, cp = i % 8;
        int c0 = 2 * cp, c1 = c0 + 1;
        float s0 = 0.0f, s1 = 0.0f;
        for (int d = 0; d < DIMN; d++) {
            float v0 = negd(l, c0, d), v1 = negd(l, c1, d);
            s0 += v0 * v0; s1 += v1 * v1;
        }
        g_d2[i] = pk2(s0, s1);
    }
    // m5 vectors + |m5|^2
    for (int i = t; i < 8 * 8; i += 256) {
        int j = i / 8, cp = i % 8;
        int c0 = 2 * cp, c1 = c0 + 1;
        ulonglong2 v;
        v.x = pk2(m5v(c0, 2 * j),     m5v(c1, 2 * j));
        v.y = pk2(m5v(c0, 2 * j + 1), m5v(c1, 2 * j + 1));
        g_m52[i] = v;
    }
    if (t < 8) {
        int c0 = 2 * t, c1 = c0 + 1;
        float s0 = 0.0f, s1 = 0.0f;
        for (int d = 0; d < DIMN; d++) {
            float v0 = m5v(c0, d), v1 = m5v(c1, d);
            s0 += v0 * v0; s1 += v1 * v1;
        }
        g_m5sq[t] = pk2(s0, s1);
    }
    // Gram: negD_k · negD_m for k<m
    for (int i = t; i < 36 * 8; i += 256) {
        int km = i / 8, cp = i % 8;
        int k = km / 6, m = km % 6;
        if (k < m) {
            int c0 = 2 * cp, c1 = c0 + 1;
            float s0 = 0.0f, s1 = 0.0f;
            for (int d = 0; d < DIMN; d++) {
                s0 += negd(k, c0, d) * negd(m, c0, d);
                s1 += negd(k, c1, d) * negd(m, c1, d);
            }
            g_G[i] = pk2(s0, s1);
        }
    }
    // negD_k · m5
    for (int i = t; i < LL * 8; i += 256) {
        int k = i / 8, cp = i % 8;
        int c0 = 2 * cp, c1 = c0 + 1;
        float s0 = 0.0f, s1 = 0.0f;
        for (int d = 0; d < DIMN; d++) {
            s0 += negd(k, c0, d) * m5v(c0, d);
            s1 += negd(k, c1, d) * m5v(c1, d);
        }
        g_Gm[i] = pk2(s0, s1);
    }

    // cov identity check
    int bad = 0;
    const float4* cv4 = (const float4*)cov;
    for (int i = t; i < CC * DIMN * DIMN / 4; i += 256) {
        float4 v = cv4[i];
        int r0 = (i * 4) % (DIMN * DIMN);
        float e0 = ((r0 % (DIMN + 1)) == 0) ? 1.0f : 0.0f;
        float e1 = (((r0 + 1) % (DIMN + 1)) == 0) ? 1.0f : 0.0f;
        float e2 = (((r0 + 2) % (DIMN + 1)) == 0) ? 1.0f : 0.0f;
        float e3 = (((r0 + 3) % (DIMN + 1)) == 0) ? 1.0f : 0.0f;
        if (v.x != e0 || v.y != e1 || v.z != e2 || v.w != e3) bad = 1;
    }
    if (bad) atomicOr(&s_bad, 1);
    __syncthreads();
    int id = (s_bad == 0) ? 1 : 0;
    if (t == 0) g_ident = id;

    int c = t;
    if (c < CC) {
        if (id) {
            g_hld[c] = 0.0f;
        } else {
            float Lm[DIMN][DIMN];
            const float* A = cov + c * DIMN * DIMN;
            #pragma unroll 1
            for (int j = 0; j < DIMN; j++) {
                float s = A[j * DIMN + j];
                #pragma unroll 1
                for (int k = 0; k < j; k++) s -= Lm[j][k] * Lm[j][k];
                float d = sqrtf(s);
                Lm[j][j] = d;
                float inv = 1.0f / d;
                #pragma unroll 1
                for (int i = j + 1; i < DIMN; i++) {
                    float s2 = A[i * DIMN + j];
                    #pragma unroll 1
                    for (int k = 0; k < j; k++) s2 -= Lm[i][k] * Lm[j][k];
                    Lm[i][j] = s2 * inv;
                }
            }
            float hld = 0.0f;
            #pragma unroll 1
            for (int j = 0; j < DIMN; j++) hld += logf(Lm[j][j]);
            g_hld[c] = hld;

            float Li[DIMN][DIMN];
            #pragma unroll 1
            for (int j = 0; j < DIMN; j++) {
                for (int i = 0; i < DIMN; i++) Li[i][j] = 0.0f;
                Li[j][j] = 1.0f / Lm[j][j];
                #pragma unroll 1
                for (int i = j + 1; i < DIMN; i++) {
                    float s3 = 0.0f;
                    #pragma unroll 1
                    for (int k = j; k < i; k++) s3 += Lm[i][k] * Li[k][j];
                    Li[i][j] = -s3 / Lm[i][i];
                }
            }
            for (int i = 0; i < DIMN; i++)
                for (int j = 0; j < DIMN; j++)
                    g_Linv[(c * DIMN + i) * DIMN + j] = Li[i][j];
        }
    }
    __syncthreads();
    if (t < 8) g_hld2[t] = pk2(g_hld[2 * t], g_hld[2 * t + 1]);
}

// ---------------- FAST kernel: identity cov, Gram expansion (no s-vector) ----------------
__global__ void __launch_bounds__(128, 6)
density_fast(const float* __restrict__ z, float* __restrict__ out, int N)
{
    if (!g_ident) return;   // uniform early exit; cold case handled by density_general

    __shared__ ulonglong2 s_negD[LL * 8 * 8];     // 6 KB
    __shared__ ulonglong2 s_m5[8 * 8];            // 1 KB
    __shared__ ulonglong2 s_parab[LL * 8];
    __shared__ u64        s_parc[LL * 8];
    __shared__ u64        s_d2[LL * 8];
    __shared__ u64        s_G[36 * 8];            // 2.25 KB
    __shared__ u64        s_Gm[LL * 8];
    __shared__ u64        s_m5sq[8];

    int t = threadIdx.x;
    for (int i = t; i < LL * 8 * 8; i += 128) s_negD[i] = g_negD2[i];
    if (t < 8 * 8) s_m5[t] = g_m52[t];
    if (t < LL * 8) { s_parab[t] = g_parab[t]; s_parc[t] = g_parc[t];
                      s_d2[t] = g_d2[t];       s_Gm[t] = g_Gm[t]; }
    for (int i = t; i < 36 * 8; i += 128) s_G[i] = g_G[i];
    if (t < 8) s_m5sq[t] = g_m5sq[t];
    __syncthreads();

    int n = blockIdx.x * 128 + t;
    if (n >= N) return;

    const float4* zr = (const float4*)(z + (size_t)n * DIMN);
    float4 q0 = zr[0], q1 = zr[1], q2 = zr[2], q3 = zr[3];
    float zf[16] = { q0.x, q0.y, q0.z, q0.w, q1.x, q1.y, q1.z, q1.w,
                     q2.x, q2.y, q2.z, q2.w, q3.x, q3.y, q3.z, q3.w };
    float zz = 0.0f;
    #pragma unroll
    for (int d = 0; d < 16; d++) zz = fmaf(zf[d], zf[d], zz);
    u64 zz2 = pk2(zz, zz);

    const float HALF_DIM_LOG2PI = 14.7030165f;
    const u64 ONE2 = pk2(1.0f, 1.0f);

    #pragma unroll 1
    for (int cp = 0; cp < 8; cp++) {
        // ---- 7 upfront dots: g0 = z·negD_0, A_m = z·negD_m (m=1..5), AF = z·m5 ----
        u64 gd0 = 0ull, A1 = 0ull, A2 = 0ull, A3 = 0ull, A4 = 0ull, A5 = 0ull, AF = 0ull;
        const ulonglong2* dp = &s_negD[cp];
        const ulonglong2* mp = &s_m5[cp];
        #pragma unroll
        for (int j = 0; j < 8; j++) {
            u64 zx = pk2(zf[2 * j],     zf[2 * j]);
            u64 zy = pk2(zf[2 * j + 1], zf[2 * j + 1]);
            ulonglong2 d0 = dp[0 * 64 + j * 8];
            ulonglong2 d1 = dp[1 * 64 + j * 8];
            ulonglong2 d2v = dp[2 * 64 + j * 8];
            ulonglong2 d3 = dp[3 * 64 + j * 8];
            ulonglong2 d4 = dp[4 * 64 + j * 8];
            ulonglong2 d5 = dp[5 * 64 + j * 8];
            ulonglong2 dm = mp[j * 8];
            gd0 = ffma2(zx, d0.x, gd0); gd0 = ffma2(zy, d0.y, gd0);
            A1  = ffma2(zx, d1.x, A1);  A1  = ffma2(zy, d1.y, A1);
            A2  = ffma2(zx, d2v.x, A2); A2  = ffma2(zy, d2v.y, A2);
            A3  = ffma2(zx, d3.x, A3);  A3  = ffma2(zy, d3.y, A3);
            A4  = ffma2(zx, d4.x, A4);  A4  = ffma2(zy, d4.y, A4);
            A5  = ffma2(zx, d5.x, A5);  A5  = ffma2(zy, d5.y, A5);
            AF  = ffma2(zx, dm.x, AF);  AF  = ffma2(zy, dm.y, AF);
        }
        // A_m^{(0)} = z·negD_m + G[0][m]  (s_0 = z + negD_0, c=1, w0=1)
        A1 = add2(A1, s_G[(0 * 6 + 1) * 8 + cp]);
        A2 = add2(A2, s_G[(0 * 6 + 2) * 8 + cp]);
        A3 = add2(A3, s_G[(0 * 6 + 3) * 8 + cp]);
        A4 = add2(A4, s_G[(0 * 6 + 4) * 8 + cp]);
        A5 = add2(A5, s_G[(0 * 6 + 5) * 8 + cp]);
        AF = add2(AF, s_Gm[0 * 8 + cp]);
        // r2_0 = |z|^2 + 2 z·negD_0 + |negD_0|^2
        u64 r2 = add2(add2(zz2, add2(gd0, gd0)), s_d2[0 * 8 + cp]);

        u64 P1p = ONE2, P2p = ONE2, f1p;

        // ---- layer k=1: tail(params 0); r2 += via A1; update A2..A5,AF with G[1][m] ----
        f1p = tail2(r2, s_parab[0 * 8 + cp], s_parc[0 * 8 + cp], P1p, P2p);
        r2 = ffma2(f1p, ffma2(f1p, r2, add2(A1, A1)), s_d2[1 * 8 + cp]);
        A2 = ffma2(f1p, A2, s_G[(1 * 6 + 2) * 8 + cp]);
        A3 = ffma2(f1p, A3, s_G[(1 * 6 + 3) * 8 + cp]);
        A4 = ffma2(f1p, A4, s_G[(1 * 6 + 4) * 8 + cp]);
        A5 = ffma2(f1p, A5, s_G[(1 * 6 + 5) * 8 + cp]);
        AF = ffma2(f1p, AF, s_Gm[1 * 8 + cp]);

        // ---- layer k=2 ----
        f1p = tail2(r2, s_parab[1 * 8 + cp], s_parc[1 * 8 + cp], P1p, P2p);
        r2 = ffma2(f1p, ffma2(f1p, r2, add2(A2, A2)), s_d2[2 * 8 + cp]);
        A3 = ffma2(f1p, A3, s_G[(2 * 6 + 3) * 8 + cp]);
        A4 = ffma2(f1p, A4, s_G[(2 * 6 + 4) * 8 + cp]);
        A5 = ffma2(f1p, A5, s_G[(2 * 6 + 5) * 8 + cp]);
        AF = ffma2(f1p, AF, s_Gm[2 * 8 + cp]);

        // ---- layer k=3 ----
        f1p = tail2(r2, s_parab[2 * 8 + cp], s_parc[2 * 8 + cp], P1p, P2p);
        r2 = ffma2(f1p, ffma2(f1p, r2, add2(A3, A3)), s_d2[3 * 8 + cp]);
        A4 = ffma2(f1p, A4, s_G[(3 * 6 + 4) * 8 + cp]);
        A5 = ffma2(f1p, A5, s_G[(3 * 6 + 5) * 8 + cp]);
        AF = ffma2(f1p, AF, s_Gm[3 * 8 + cp]);

        // ---- layer k=4 ----
        f1p = tail2(r2, s_parab[3 * 8 + cp], s_parc[3 * 8 + cp], P1p, P2p);
        r2 = ffma2(f1p, ffma2(f1p, r2, add2(A4, A4)), s_d2[4 * 8 + cp]);
        A5 = ffma2(f1p, A5, s_G[(4 * 6 + 5) * 8 + cp]);
        AF = ffma2(f1p, AF, s_Gm[4 * 8 + cp]);

        // ---- layer k=5 ----
        f1p = tail2(r2, s_parab[4 * 8 + cp], s_parc[4 * 8 + cp], P1p, P2p);
        r2 = ffma2(f1p, ffma2(f1p, r2, add2(A5, A5)), s_d2[5 * 8 + cp]);
        AF = ffma2(f1p, AF, s_Gm[5 * 8 + cp]);

        // ---- final transform (params 5): q = f1^2 r2 + 2 f1 (s5·m5) + |m5|^2 ----
        f1p = tail2(r2, s_parab[5 * 8 + cp], s_parc[5 * 8 + cp], P1p, P2p);
        u64 qp = ffma2(f1p, ffma2(f1p, r2, add2(AF, AF)), s_m5sq[cp]);
        float qA, qB; up2(qA, qB, qp);

        // log_det_jac total = log(P1^15 * P2)
        u64 p2  = mul2(P1p, P1p);
        u64 p4  = mul2(p2, p2);
        u64 p8  = mul2(p4, p4);
        u64 g   = mul2(mul2(mul2(p8, p4), mul2(p2, P1p)), P2p);
        float gA, gB; up2(gA, gB, g);
        float vA = fmaf(-0.5f, qA, -HALF_DIM_LOG2PI) + __logf(gA);
        float vB = fmaf(-0.5f, qB, -HALF_DIM_LOG2PI) + __logf(gB);
        if (vA != vA) vA = __int_as_float(0xff800000);  // NaN -> -inf
        if (vB != vB) vB = __int_as_float(0xff800000);

        *(float2*)(out + (size_t)n * CC + 2 * cp) = make_float2(vA, vB);
    }
}

// ---------------- GENERAL kernel: non-identity cov (R16 structure; early-exits if ident) ----------------
__global__ void __launch_bounds__(128, 5)
density_general(const float* __restrict__ z, float* __restrict__ out, int N)
{
    if (g_ident) return;   // hot case handled by density_fast

    __shared__ ulonglong2 s_negD[LL * 8 * 8];
    __shared__ ulonglong2 s_m5[8 * 8];
    __shared__ ulonglong2 s_parab[LL * 8];
    __shared__ u64        s_parc[LL * 8];
    __shared__ u64        s_hld2[8];

    int t = threadIdx.x;
    for (int i = t; i < LL * 8 * 8; i += 128) s_negD[i] = g_negD2[i];
    if (t < 8 * 8) s_m5[t] = g_m52[t];
    if (t < LL * 8) { s_parab[t] = g_parab[t]; s_parc[t] = g_parc[t]; }
    if (t < 8) s_hld2[t] = g_hld2[t];
    __syncthreads();

    int n = blockIdx.x * 128 + t;
    if (n >= N) return;

    const float4* zr = (const float4*)(z + (size_t)n * DIMN);
    float4 q0 = zr[0], q1 = zr[1], q2 = zr[2], q3 = zr[3];
    float zf[16] = { q0.x, q0.y, q0.z, q0.w, q1.x, q1.y, q1.z, q1.w,
                     q2.x, q2.y, q2.z, q2.w, q3.x, q3.y, q3.z, q3.w };

    const float HALF_DIM_LOG2PI = 14.7030165f;
    const u64 ONE2 = pk2(1.0f, 1.0f);

    #pragma unroll 1
    for (int cp = 0; cp < 8; cp++) {
        const ulonglong2* dp = &s_negD[cp];
        u64 s[16];
        u64 e0 = 0ull, e1 = 0ull;
        #pragma unroll
        for (int j = 0; j < 8; j++) {
            ulonglong2 dd = dp[j * 8];
            s[2 * j]     = add2(pk2(zf[2 * j],     zf[2 * j]),     dd.x);
            s[2 * j + 1] = add2(pk2(zf[2 * j + 1], zf[2 * j + 1]), dd.y);
            e0 = ffma2(s[2 * j],     s[2 * j],     e0);
            e1 = ffma2(s[2 * j + 1], s[2 * j + 1], e1);
        }
        u64 r2p = add2(e0, e1);
        u64 P1p = ONE2, P2p = ONE2, f1p;

        #pragma unroll
        for (int l = 1; l < LL; l++) {
            const ulonglong2* dl = dp + l * 64;
            f1p = tail2(r2p, s_parab[(l - 1) * 8 + cp], s_parc[(l - 1) * 8 + cp], P1p, P2p);
            e0 = 0ull; e1 = 0ull;
            #pragma unroll
            for (int j = 0; j < 8; j++) {
                ulonglong2 dd = dl[j * 8];
                s[2 * j]     = ffma2(f1p, s[2 * j],     dd.x);
                s[2 * j + 1] = ffma2(f1p, s[2 * j + 1], dd.y);
                e0 = ffma2(s[2 * j],     s[2 * j],     e0);
                e1 = ffma2(s[2 * j + 1], s[2 * j + 1], e1);
            }
            r2p = add2(e0, e1);
        }

        const ulonglong2* mp = &s_m5[cp];
        f1p = tail2(r2p, s_parab[5 * 8 + cp], s_parc[5 * 8 + cp], P1p, P2p);

        float drA[DIMN], drB[DIMN];
        #pragma unroll
        for (int j = 0; j < 8; j++) {
            ulonglong2 mm = mp[j * 8];
            u64 dx = ffma2(f1p, s[2 * j],     mm.x);
            u64 dy = ffma2(f1p, s[2 * j + 1], mm.y);
            up2(drA[2 * j],     drB[2 * j],     dx);
            up2(drA[2 * j + 1], drB[2 * j + 1], dy);
        }
        float qA = 0.0f, qB = 0.0f;
        const float* LpA = &g_Linv[2 * cp * DIMN * DIMN];
        const float* LpB = LpA + DIMN * DIMN;
        #pragma unroll 1
        for (int j = 0; j < DIMN; j++) {
            float sa = 0.0f, sb = 0.0f;
            #pragma unroll 1
            for (int i = 0; i <= j; i++) {
                sa = fmaf(LpA[j * DIMN + i], drA[i], sa);
                sb = fmaf(LpB[j * DIMN + i], drB[i], sb);
            }
            qA = fmaf(sa, sa, qA);
            qB = fmaf(sb, sb, qB);
        }

        u64 p2  = mul2(P1p, P1p);
        u64 p4  = mul2(p2, p2);
        u64 p8  = mul2(p4, p4);
        u64 g   = mul2(mul2(mul2(p8, p4), mul2(p2, P1p)), P2p);
        float gA, gB; up2(gA, gB, g);
        float hldA, hldB; up2(hldA, hldB, s_hld2[cp]);
        float vA = fmaf(-0.5f, qA, -HALF_DIM_LOG2PI) - hldA + __logf(gA);
        float vB = fmaf(-0.5f, qB, -HALF_DIM_LOG2PI) - hldB + __logf(gB);
        if (vA != vA) vA = __int_as_float(0xff800000);
        if (vB != vB) vB = __int_as_float(0xff800000);

        *(float2*)(out + (size_t)n * CC + 2 * cp) = make_float2(vA, vB);
    }
}

// ---------------- launch ----------------
extern "C" void kernel_launch(void* const* d_in, const int* in_sizes, int n_in,
                              void* d_out, int out_size) {
    const float* z    = (const float*)d_in[0];
    const float* z0   = (const float*)d_in[1];
    const float* la   = (const float*)d_in[2];
    const float* be   = (const float*)d_in[3];
    const float* mean = (const float*)d_in[4];
    const float* cov  = (const float*)d_in[5];
    float* out = (float*)d_out;

    int N = in_sizes[0] / DIMN;
    int blocks = (N + 127) / 128;

    setup_kernel<<<1, 256>>>(la, be, z0, mean, cov);
    density_fast<<<blocks, 128>>>(z, out, N);
    density_general<<<blocks, 128>>>(z, out, N);
}